// round 7
// baseline (speedup 1.0000x reference)
#include <cuda_runtime.h>
#include <cuda_fp16.h>
#include <cuda_bf16.h>
#include <mma.h>
#include <stdint.h>

using namespace nvcuda;

// ---------------- problem constants ----------------
#define NMAX 50000
#define EMAX 800000
#define D    128
#define TSTRIDE 72        // smem tile stride (halves): 144B rows, LDSM conflict-free
#define BK 64
#define TILE_BYTES (128 * TSTRIDE * 2)      // 18432 B per fp16 tile
#define BUF_BYTES  (3 * TILE_BYTES)         // 55296 B per stage (A, Whi, Wlo)
#define SMEM_TOTAL (2 * BUF_BYTES)          // 110592 B (Csm 64KB reuses this)

// ---------------- device scratch ----------------
__device__ int   g_cnt[NMAX];
__device__ int   g_rp[NMAX];
__device__ int   g_fill[NMAX];
__device__ float g_inv[NMAX];
__device__ int   g_col[EMAX];
__device__ int   g_tot;
__device__ int   g_is64;
__device__ __align__(16) __half g_act[NMAX * D];   // fp16 activations (gather + GEMM H)
__device__ __align__(16) __half g_agg[NMAX * D];   // fp16 aggregated means (GEMM A)
__device__ __align__(16) __half g_Whi[6 * D * D];
__device__ __align__(16) __half g_Wlo[6 * D * D];

// ---------------- helpers ----------------
__device__ __forceinline__ unsigned smem_u32(const void* p) {
    unsigned a;
    asm("{ .reg .u64 t; cvta.to.shared.u64 t, %1; cvt.u32.u64 %0, t; }"
        : "=r"(a) : "l"(p));
    return a;
}

__device__ __forceinline__ void cp16(unsigned sdst, const void* gsrc) {
    asm volatile("cp.async.cg.shared.global [%0], [%1], 16;"
                 :: "r"(sdst), "l"(gsrc));
}

// ---------------- init: zero counters + edge dtype detection ----------------
__global__ void init_kernel(const void* ei, int E, int n) {
    int i = blockIdx.x * blockDim.x + threadIdx.x;
    if (i < n) g_cnt[i] = 0;
    if (i == 0) g_tot = 0;
    if (blockIdx.x == 0) {
        const int* p = (const int*)ei;
        int m = min(E, 2048);
        int bad = 0;
        for (int k = threadIdx.x; k < m; k += blockDim.x) bad |= p[2 * k + 1];
        __shared__ int s;
        if (threadIdx.x == 0) s = 0;
        __syncthreads();
        atomicOr(&s, bad);
        __syncthreads();
        if (threadIdx.x == 0) g_is64 = (s == 0) ? 1 : 0;
    }
}

__device__ __forceinline__ int load_idx(const void* ei, long long pos) {
    if (g_is64) return (int)((const long long*)ei)[pos];
    return ((const int*)ei)[pos];
}

// ---------------- CSR build ----------------
__global__ void hist_kernel(const void* ei, int E) {
    int e = blockIdx.x * blockDim.x + threadIdx.x;
    if (e >= E) return;
    int d = load_idx(ei, (long long)E + e);
    atomicAdd(&g_cnt[d], 1);
}

__global__ void assign_kernel(int n) {
    int i = blockIdx.x * blockDim.x + threadIdx.x;
    int lane = threadIdx.x & 31;
    int c = (i < n) ? g_cnt[i] : 0;
    int x = c;
    #pragma unroll
    for (int off = 1; off < 32; off <<= 1) {
        int y = __shfl_up_sync(0xffffffffu, x, off);
        if (lane >= off) x += y;
    }
    int wsum = __shfl_sync(0xffffffffu, x, 31);
    int base = 0;
    if (lane == 31) base = atomicAdd(&g_tot, wsum);
    base = __shfl_sync(0xffffffffu, base, 31);
    int excl = base + x - c;
    if (i < n) {
        g_rp[i]   = excl;
        g_fill[i] = excl;
        g_inv[i]  = 1.0f / ((c > 0) ? (float)c : 1.0f);
    }
}

__global__ void fill_kernel(const void* ei, int E) {
    int e = blockIdx.x * blockDim.x + threadIdx.x;
    if (e >= E) return;
    int s = load_idx(ei, e);
    int d = load_idx(ei, (long long)E + e);
    int idx = atomicAdd(&g_fill[d], 1);
    g_col[idx] = s;
}

// ---------------- conversions ----------------
__global__ void xconv_kernel(const float* __restrict__ x,
                             __half* __restrict__ act, int total4) {
    int i = blockIdx.x * blockDim.x + threadIdx.x;
    if (i >= total4) return;
    float4 v = *(const float4*)(x + 4 * i);
    __half2 a0 = __floats2half2_rn(v.x, v.y);
    __half2 a1 = __floats2half2_rn(v.z, v.w);
    *(uint2*)(act + 4 * i) = make_uint2(*(unsigned*)&a0, *(unsigned*)&a1);
}

__global__ void wconv_kernel(const float* __restrict__ w0, const float* __restrict__ w1,
                             const float* __restrict__ w2, const float* __restrict__ w3,
                             const float* __restrict__ w4, const float* __restrict__ w5) {
    int i = blockIdx.x * blockDim.x + threadIdx.x;
    if (i >= 6 * D * D) return;
    int m = i >> 14, off = i & (D * D - 1);
    const float* src;
    switch (m) {
        case 0: src = w0; break; case 1: src = w1; break;
        case 2: src = w2; break; case 3: src = w3; break;
        case 4: src = w4; break; default: src = w5; break;
    }
    float v = src[off];
    __half h = __float2half_rn(v);
    __half l = __float2half_rn(v - __half2float(h));
    g_Whi[i] = h;
    g_Wlo[i] = l;
}

// ---------------- mean aggregation (fp16 gather, fp32 accumulate) ----------------
__device__ __forceinline__ void acc_add(float4& acc, uint2 v) {
    __half2 h0 = *(__half2*)&v.x;
    __half2 h1 = *(__half2*)&v.y;
    float2 f0 = __half22float2(h0);
    float2 f1 = __half22float2(h1);
    acc.x += f0.x; acc.y += f0.y; acc.z += f1.x; acc.w += f1.y;
}

__global__ void agg_kernel(const __half* __restrict__ hin,
                           __half* __restrict__ aout, int n) {
    int w = (blockIdx.x * blockDim.x + threadIdx.x) >> 5;
    int lane = threadIdx.x & 31;
    if (w >= n) return;
    int start = g_rp[w];
    int end = start + g_cnt[w];
    float4 acc = make_float4(0.f, 0.f, 0.f, 0.f);
    for (int e = start; e < end; e += 32) {
        int myc = (e + lane < end) ? g_col[e + lane] : 0;
        int m = min(32, end - e);
        int j = 0;
        for (; j + 4 <= m; j += 4) {
            int s0 = __shfl_sync(0xffffffffu, myc, j + 0);
            int s1 = __shfl_sync(0xffffffffu, myc, j + 1);
            int s2 = __shfl_sync(0xffffffffu, myc, j + 2);
            int s3 = __shfl_sync(0xffffffffu, myc, j + 3);
            uint2 v0 = *(const uint2*)(hin + (size_t)s0 * D + 4 * lane);
            uint2 v1 = *(const uint2*)(hin + (size_t)s1 * D + 4 * lane);
            uint2 v2 = *(const uint2*)(hin + (size_t)s2 * D + 4 * lane);
            uint2 v3 = *(const uint2*)(hin + (size_t)s3 * D + 4 * lane);
            acc_add(acc, v0); acc_add(acc, v1);
            acc_add(acc, v2); acc_add(acc, v3);
        }
        for (; j < m; ++j) {
            int s = __shfl_sync(0xffffffffu, myc, j);
            uint2 v = *(const uint2*)(hin + (size_t)s * D + 4 * lane);
            acc_add(acc, v);
        }
    }
    float inv = g_inv[w];
    __half2 p0 = __floats2half2_rn(acc.x * inv, acc.y * inv);
    __half2 p1 = __floats2half2_rn(acc.z * inv, acc.w * inv);
    *(uint2*)(aout + (size_t)w * D + 4 * lane) = make_uint2(*(unsigned*)&p0, *(unsigned*)&p1);
}

// ---------------- tensor-core GEMM: 4 warps, 64x64 warp tiles, BK=64 ----------------
// out[m][o] = [relu]( sum_k A[m][k]*Wl[o][k] + H[m][k]*Wr[o][k] + b[o] )
// fp16 A single, fp16 W split: C += A*Whi + A*Wlo. 4 chunks (2 src x 2 k).
__global__ __launch_bounds__(128)
void gemm_kernel(const __half* __restrict__ Agg, const __half* __restrict__ Act,
                 const __half* __restrict__ Wlhi, const __half* __restrict__ Wllo,
                 const __half* __restrict__ Wrhi, const __half* __restrict__ Wrlo,
                 const float* __restrict__ bias,
                 float* __restrict__ out, __half* __restrict__ actout,
                 int n, int relu, int fin) {
    extern __shared__ char smraw[];
    float* Csm = (float*)smraw;

    int tid = threadIdx.x;
    int wid = tid >> 5;
    int warp_m = wid & 1;        // 2 M groups of 64
    int warp_n = wid >> 1;       // 2 N groups of 64
    int m0 = blockIdx.x * 128;

    wmma::fragment<wmma::accumulator, 16, 16, 16, float> acc[4][4];
    #pragma unroll
    for (int i = 0; i < 4; ++i)
        #pragma unroll
        for (int j = 0; j < 4; ++j) wmma::fill_fragment(acc[i][j], 0.0f);

    int grow = m0 + tid;                       // row this thread copies (0..127)
    int arow = (grow < n) ? grow : (n - 1);    // clamp; garbage rows dropped in epilogue
    unsigned soff = (unsigned)tid * TSTRIDE * 2;
    unsigned sbase = smem_u32(smraw);

    #define ISSUE(c, b) do {                                                   \
        int s_ = (c) >> 1, k0_ = ((c) & 1) * BK;                               \
        const __half* a_  = s_ ? Act : Agg;                                    \
        const __half* wh_ = s_ ? Wrhi : Wlhi;                                  \
        const __half* wl_ = s_ ? Wrlo : Wllo;                                  \
        unsigned bb_ = sbase + (b) * BUF_BYTES;                                \
        size_t ga_ = (size_t)arow * D + k0_;                                   \
        size_t gw_ = (size_t)tid * D + k0_;                                    \
        _Pragma("unroll")                                                      \
        for (int q = 0; q < 8; ++q) {                                          \
            cp16(bb_ + 0 * TILE_BYTES + soff + q * 16, a_  + ga_ + q * 8);     \
            cp16(bb_ + 1 * TILE_BYTES + soff + q * 16, wh_ + gw_ + q * 8);     \
            cp16(bb_ + 2 * TILE_BYTES + soff + q * 16, wl_ + gw_ + q * 8);     \
        }                                                                      \
        asm volatile("cp.async.commit_group;");                                \
    } while (0)

    ISSUE(0, 0);

    for (int c = 0; c < 4; ++c) {
        asm volatile("cp.async.wait_group 0;");
        __syncthreads();
        if (c < 3) ISSUE(c + 1, (c + 1) & 1);

        char* bb = smraw + (c & 1) * BUF_BYTES;
        __half* As   = (__half*)(bb + 0 * TILE_BYTES);
        __half* Ws_h = (__half*)(bb + 1 * TILE_BYTES);
        __half* Ws_l = (__half*)(bb + 2 * TILE_BYTES);

        #pragma unroll
        for (int kk = 0; kk < BK; kk += 16) {
            wmma::fragment<wmma::matrix_a, 16, 16, 16, __half, wmma::row_major> a[4];
            #pragma unroll
            for (int i = 0; i < 4; ++i)
                wmma::load_matrix_sync(a[i], As + (warp_m * 64 + i * 16) * TSTRIDE + kk, TSTRIDE);
            #pragma unroll
            for (int j = 0; j < 4; ++j) {
                wmma::fragment<wmma::matrix_b, 16, 16, 16, __half, wmma::col_major> b_hi, b_lo;
                int orow = warp_n * 64 + j * 16;
                wmma::load_matrix_sync(b_hi, Ws_h + orow * TSTRIDE + kk, TSTRIDE);
                wmma::load_matrix_sync(b_lo, Ws_l + orow * TSTRIDE + kk, TSTRIDE);
                #pragma unroll
                for (int i = 0; i < 4; ++i) {
                    wmma::mma_sync(acc[i][j], a[i], b_hi, acc[i][j]);
                    wmma::mma_sync(acc[i][j], a[i], b_lo, acc[i][j]);
                }
            }
        }
    }
    __syncthreads();
    #pragma unroll
    for (int i = 0; i < 4; ++i)
        #pragma unroll
        for (int j = 0; j < 4; ++j)
            wmma::store_matrix_sync(Csm + (warp_m * 64 + i * 16) * 128 + warp_n * 64 + j * 16,
                                    acc[i][j], 128, wmma::mem_row_major);
    __syncthreads();

    #pragma unroll
    for (int it = 0; it < 32; ++it) {
        int e = (it * 128 + tid) * 4;
        int row = e >> 7;
        int col = e & 127;
        int gr = m0 + row;
        if (gr >= n) continue;
        float4 v = *(float4*)(Csm + e);
        float4 b = *(const float4*)(bias + col);
        v.x += b.x; v.y += b.y; v.z += b.z; v.w += b.w;
        if (relu) {
            v.x = fmaxf(v.x, 0.f); v.y = fmaxf(v.y, 0.f);
            v.z = fmaxf(v.z, 0.f); v.w = fmaxf(v.w, 0.f);
        }
        size_t go = (size_t)gr * D + col;
        if (fin) {
            *(float4*)(out + go) = v;
        } else {
            __half2 a0 = __floats2half2_rn(v.x, v.y);
            __half2 a1 = __floats2half2_rn(v.z, v.w);
            *(uint2*)(actout + go) = make_uint2(*(unsigned*)&a0, *(unsigned*)&a1);
        }
    }
}

// ---------------- launch ----------------
extern "C" void kernel_launch(void* const* d_in, const int* in_sizes, int n_in,
                              void* d_out, int out_size) {
    const float* x   = (const float*)d_in[0];
    const void*  ei  = d_in[1];
    const float* W1l = (const float*)d_in[2];
    const float* b1  = (const float*)d_in[3];
    const float* W1r = (const float*)d_in[4];
    const float* W2l = (const float*)d_in[5];
    const float* b2  = (const float*)d_in[6];
    const float* W2r = (const float*)d_in[7];
    const float* W3l = (const float*)d_in[8];
    const float* b3  = (const float*)d_in[9];
    const float* W3r = (const float*)d_in[10];
    float* out = (float*)d_out;

    int n = in_sizes[0] / D;
    int E = in_sizes[1] / 2;

    __half *actp, *aggp, *whip, *wlop;
    cudaGetSymbolAddress((void**)&actp, g_act);
    cudaGetSymbolAddress((void**)&aggp, g_agg);
    cudaGetSymbolAddress((void**)&whip, g_Whi);
    cudaGetSymbolAddress((void**)&wlop, g_Wlo);

    cudaFuncSetAttribute(gemm_kernel, cudaFuncAttributeMaxDynamicSharedMemorySize, SMEM_TOTAL);

    // CSR build
    init_kernel<<<(n + 255) / 256, 256>>>(ei, E, n);
    hist_kernel<<<(E + 255) / 256, 256>>>(ei, E);
    assign_kernel<<<(n + 255) / 256, 256>>>(n);
    fill_kernel<<<(E + 255) / 256, 256>>>(ei, E);

    // conversions
    wconv_kernel<<<(6 * D * D + 255) / 256, 256>>>(W1l, W1r, W2l, W2r, W3l, W3r);
    int total4 = n * D / 4;
    xconv_kernel<<<(total4 + 255) / 256, 256>>>(x, actp, total4);

    int agg_blocks  = (n * 32 + 255) / 256;
    int gemm_blocks = (n + 127) / 128;

    // layer 1
    agg_kernel<<<agg_blocks, 256>>>(actp, aggp, n);
    gemm_kernel<<<gemm_blocks, 128, SMEM_TOTAL>>>(aggp, actp,
        whip + 0 * D * D, wlop + 0 * D * D, whip + 1 * D * D, wlop + 1 * D * D,
        b1, out, actp, n, 1, 0);
    // layer 2
    agg_kernel<<<agg_blocks, 256>>>(actp, aggp, n);
    gemm_kernel<<<gemm_blocks, 128, SMEM_TOTAL>>>(aggp, actp,
        whip + 2 * D * D, wlop + 2 * D * D, whip + 3 * D * D, wlop + 3 * D * D,
        b2, out, actp, n, 1, 0);
    // layer 3 (final: fp32 out)
    agg_kernel<<<agg_blocks, 256>>>(actp, aggp, n);
    gemm_kernel<<<gemm_blocks, 128, SMEM_TOTAL>>>(aggp, actp,
        whip + 4 * D * D, wlop + 4 * D * D, whip + 5 * D * D, wlop + 5 * D * D,
        b3, out, actp, n, 0, 1);
}

// round 8
// speedup vs baseline: 1.2764x; 1.2764x over previous
#include <cuda_runtime.h>
#include <cuda_fp16.h>
#include <cuda_bf16.h>
#include <mma.h>
#include <stdint.h>

using namespace nvcuda;

// ---------------- problem constants ----------------
#define NMAX 50000
#define EMAX 800000
#define D    128
#define TSTRIDE 40        // smem tile stride (halves): 80B rows
#define BK 32
#define TILE_BYTES (128 * TSTRIDE * 2)      // 10240 B per fp16 tile
#define BUF_BYTES  (2 * TILE_BYTES)         // 20480 B per stage (A, W)
#define SMEM_TOTAL 65536                    // Csm (128*128*4) dominates

// ---------------- device scratch ----------------
__device__ int   g_cnt[NMAX];
__device__ int   g_rp[NMAX];
__device__ int   g_fill[NMAX];
__device__ float g_inv[NMAX];
__device__ int   g_col[EMAX];
__device__ int   g_tot;
__device__ int   g_is64;
__device__ __align__(16) __half g_act[NMAX * D];   // fp16 activations
__device__ __align__(16) __half g_agg[NMAX * D];   // fp16 aggregated means
__device__ __align__(16) __half g_W[6 * D * D];    // fp16 weights

// ---------------- helpers ----------------
__device__ __forceinline__ unsigned smem_u32(const void* p) {
    unsigned a;
    asm("{ .reg .u64 t; cvta.to.shared.u64 t, %1; cvt.u32.u64 %0, t; }"
        : "=r"(a) : "l"(p));
    return a;
}

__device__ __forceinline__ void cp16(unsigned sdst, const void* gsrc) {
    asm volatile("cp.async.cg.shared.global [%0], [%1], 16;"
                 :: "r"(sdst), "l"(gsrc));
}

// ---------------- edge-index dtype detection ----------------
__global__ void detect_kernel(const void* ei, int E) {
    const int* p = (const int*)ei;
    int t = threadIdx.x;
    int m = min(E, 2048);
    int bad = 0;
    for (int i = t; i < m; i += blockDim.x) bad |= p[2 * i + 1];
    __shared__ int s;
    if (t == 0) s = 0;
    __syncthreads();
    atomicOr(&s, bad);
    __syncthreads();
    if (t == 0) g_is64 = (s == 0) ? 1 : 0;
}

__device__ __forceinline__ int load_idx(const void* ei, long long pos) {
    if (g_is64) return (int)((const long long*)ei)[pos];
    return ((const int*)ei)[pos];
}

// ---------------- CSR build (4 edges/thread for atomic MLP) ----------------
__global__ void hist_kernel(const void* ei, int E) {
    int e0 = 4 * (blockIdx.x * blockDim.x + threadIdx.x);
    if (e0 >= E) return;
    int cnt = min(4, E - e0);
    int d[4];
    #pragma unroll
    for (int i = 0; i < 4; ++i)
        if (i < cnt) d[i] = load_idx(ei, (long long)E + e0 + i);
    #pragma unroll
    for (int i = 0; i < 4; ++i)
        if (i < cnt) atomicAdd(&g_cnt[d[i]], 1);
}

__global__ void assign_kernel(int n) {
    int i = blockIdx.x * blockDim.x + threadIdx.x;
    int lane = threadIdx.x & 31;
    int c = (i < n) ? g_cnt[i] : 0;
    int x = c;
    #pragma unroll
    for (int off = 1; off < 32; off <<= 1) {
        int y = __shfl_up_sync(0xffffffffu, x, off);
        if (lane >= off) x += y;
    }
    int wsum = __shfl_sync(0xffffffffu, x, 31);
    int base = 0;
    if (lane == 31) base = atomicAdd(&g_tot, wsum);
    base = __shfl_sync(0xffffffffu, base, 31);
    int excl = base + x - c;
    if (i < n) {
        g_rp[i]   = excl;
        g_fill[i] = excl;
        g_inv[i]  = 1.0f / ((c > 0) ? (float)c : 1.0f);
    }
}

__global__ void fill_kernel(const void* ei, int E) {
    int e0 = 4 * (blockIdx.x * blockDim.x + threadIdx.x);
    if (e0 >= E) return;
    int cnt = min(4, E - e0);
    int s[4], d[4], idx[4];
    #pragma unroll
    for (int i = 0; i < 4; ++i)
        if (i < cnt) {
            s[i] = load_idx(ei, e0 + i);
            d[i] = load_idx(ei, (long long)E + e0 + i);
        }
    #pragma unroll
    for (int i = 0; i < 4; ++i)
        if (i < cnt) idx[i] = atomicAdd(&g_fill[d[i]], 1);
    #pragma unroll
    for (int i = 0; i < 4; ++i)
        if (i < cnt) g_col[idx[i]] = s[i];
}

// ---------------- conversions ----------------
__global__ void xconv_kernel(const float* __restrict__ x,
                             __half* __restrict__ act, int total4) {
    int i = blockIdx.x * blockDim.x + threadIdx.x;
    if (i >= total4) return;
    float4 v = *(const float4*)(x + 4 * i);
    __half2 a0 = __floats2half2_rn(v.x, v.y);
    __half2 a1 = __floats2half2_rn(v.z, v.w);
    *(uint2*)(act + 4 * i) = make_uint2(*(unsigned*)&a0, *(unsigned*)&a1);
}

__global__ void wconv_kernel(const float* __restrict__ w0, const float* __restrict__ w1,
                             const float* __restrict__ w2, const float* __restrict__ w3,
                             const float* __restrict__ w4, const float* __restrict__ w5) {
    int i = blockIdx.x * blockDim.x + threadIdx.x;
    if (i >= 6 * D * D) return;
    int m = i >> 14, off = i & (D * D - 1);
    const float* src;
    switch (m) {
        case 0: src = w0; break; case 1: src = w1; break;
        case 2: src = w2; break; case 3: src = w3; break;
        case 4: src = w4; break; default: src = w5; break;
    }
    g_W[i] = __float2half_rn(src[off]);
}

// ---------------- mean aggregation (fp16 gather, fp32 accumulate) ----------------
__device__ __forceinline__ void acc_add(float4& acc, uint2 v) {
    __half2 h0 = *(__half2*)&v.x;
    __half2 h1 = *(__half2*)&v.y;
    float2 f0 = __half22float2(h0);
    float2 f1 = __half22float2(h1);
    acc.x += f0.x; acc.y += f0.y; acc.z += f1.x; acc.w += f1.y;
}

__global__ void agg_kernel(const __half* __restrict__ hin,
                           __half* __restrict__ aout, int n) {
    int w = (blockIdx.x * blockDim.x + threadIdx.x) >> 5;
    int lane = threadIdx.x & 31;
    if (w >= n) return;
    int start = g_rp[w];
    int end = start + g_cnt[w];
    float4 acc = make_float4(0.f, 0.f, 0.f, 0.f);
    for (int e = start; e < end; e += 32) {
        int myc = (e + lane < end) ? g_col[e + lane] : 0;
        int m = min(32, end - e);
        int j = 0;
        for (; j + 4 <= m; j += 4) {
            int s0 = __shfl_sync(0xffffffffu, myc, j + 0);
            int s1 = __shfl_sync(0xffffffffu, myc, j + 1);
            int s2 = __shfl_sync(0xffffffffu, myc, j + 2);
            int s3 = __shfl_sync(0xffffffffu, myc, j + 3);
            uint2 v0 = *(const uint2*)(hin + (size_t)s0 * D + 4 * lane);
            uint2 v1 = *(const uint2*)(hin + (size_t)s1 * D + 4 * lane);
            uint2 v2 = *(const uint2*)(hin + (size_t)s2 * D + 4 * lane);
            uint2 v3 = *(const uint2*)(hin + (size_t)s3 * D + 4 * lane);
            acc_add(acc, v0); acc_add(acc, v1);
            acc_add(acc, v2); acc_add(acc, v3);
        }
        for (; j < m; ++j) {
            int s = __shfl_sync(0xffffffffu, myc, j);
            uint2 v = *(const uint2*)(hin + (size_t)s * D + 4 * lane);
            acc_add(acc, v);
        }
    }
    float inv = g_inv[w];
    __half2 p0 = __floats2half2_rn(acc.x * inv, acc.y * inv);
    __half2 p1 = __floats2half2_rn(acc.z * inv, acc.w * inv);
    *(uint2*)(aout + (size_t)w * D + 4 * lane) = make_uint2(*(unsigned*)&p0, *(unsigned*)&p1);
}

// ---------------- tensor-core GEMM (round-5 shape, single fp16 W) ----------------
// out[m][o] = [relu]( sum_k A[m][k]*Wl[o][k] + H[m][k]*Wr[o][k] + b[o] )
// Block 128x128, 256 threads, 8 warps, warp tile 32x64. 8 chunks (2 src x 4 k).
__global__ __launch_bounds__(256)
void gemm_kernel(const __half* __restrict__ Agg, const __half* __restrict__ Act,
                 const __half* __restrict__ Wl, const __half* __restrict__ Wr,
                 const float* __restrict__ bias,
                 float* __restrict__ out, __half* __restrict__ actout,
                 int n, int relu, int fin) {
    extern __shared__ char smraw[];
    float* Csm = (float*)smraw;

    int tid = threadIdx.x;
    int wid = tid >> 5;
    int warp_m = wid & 3;
    int warp_n = wid >> 2;
    int m0 = blockIdx.x * 128;

    wmma::fragment<wmma::accumulator, 16, 16, 16, float> acc[2][4];
    #pragma unroll
    for (int i = 0; i < 2; ++i)
        #pragma unroll
        for (int j = 0; j < 4; ++j) wmma::fill_fragment(acc[i][j], 0.0f);

    int lrow = tid >> 1;          // 0..127
    int lcol = (tid & 1) * 16;    // 0 or 16
    int grow = m0 + lrow;
    int arow = (grow < n) ? grow : (n - 1);   // clamp; garbage rows dropped in epilogue
    unsigned soff = (unsigned)(lrow * TSTRIDE + lcol) * 2;
    unsigned sbase = smem_u32(smraw);

    #define ISSUE(c, b) do {                                                   \
        int s_ = (c) >> 2, k0_ = ((c) & 3) * BK;                               \
        const __half* a_ = s_ ? Act : Agg;                                     \
        const __half* w_ = s_ ? Wr  : Wl;                                      \
        unsigned bb_ = sbase + (b) * BUF_BYTES;                                \
        size_t ga_ = (size_t)arow * D + k0_ + lcol;                            \
        size_t gw_ = (size_t)lrow * D + k0_ + lcol;                            \
        cp16(bb_ + 0 * TILE_BYTES + soff,      a_ + ga_);                      \
        cp16(bb_ + 0 * TILE_BYTES + soff + 16, a_ + ga_ + 8);                  \
        cp16(bb_ + 1 * TILE_BYTES + soff,      w_ + gw_);                      \
        cp16(bb_ + 1 * TILE_BYTES + soff + 16, w_ + gw_ + 8);                  \
        asm volatile("cp.async.commit_group;");                                \
    } while (0)

    ISSUE(0, 0);

    for (int c = 0; c < 8; ++c) {
        asm volatile("cp.async.wait_group 0;");
        __syncthreads();
        if (c < 7) ISSUE(c + 1, (c + 1) & 1);

        char* bb = smraw + (c & 1) * BUF_BYTES;
        __half* As = (__half*)(bb + 0 * TILE_BYTES);
        __half* Ws = (__half*)(bb + 1 * TILE_BYTES);

        #pragma unroll
        for (int kk = 0; kk < BK; kk += 16) {
            wmma::fragment<wmma::matrix_a, 16, 16, 16, __half, wmma::row_major> a[2];
            #pragma unroll
            for (int i = 0; i < 2; ++i)
                wmma::load_matrix_sync(a[i], As + (warp_m * 32 + i * 16) * TSTRIDE + kk, TSTRIDE);
            #pragma unroll
            for (int j = 0; j < 4; ++j) {
                wmma::fragment<wmma::matrix_b, 16, 16, 16, __half, wmma::col_major> b;
                wmma::load_matrix_sync(b, Ws + (warp_n * 64 + j * 16) * TSTRIDE + kk, TSTRIDE);
                #pragma unroll
                for (int i = 0; i < 2; ++i)
                    wmma::mma_sync(acc[i][j], a[i], b, acc[i][j]);
            }
        }
    }
    __syncthreads();
    #pragma unroll
    for (int i = 0; i < 2; ++i)
        #pragma unroll
        for (int j = 0; j < 4; ++j)
            wmma::store_matrix_sync(Csm + (warp_m * 32 + i * 16) * 128 + warp_n * 64 + j * 16,
                                    acc[i][j], 128, wmma::mem_row_major);
    __syncthreads();

    #pragma unroll
    for (int it = 0; it < 16; ++it) {
        int e = (it * 256 + tid) * 4;
        int row = e >> 7;
        int col = e & 127;
        int gr = m0 + row;
        if (gr >= n) continue;
        float4 v = *(float4*)(Csm + e);
        float4 b = *(const float4*)(bias + col);
        v.x += b.x; v.y += b.y; v.z += b.z; v.w += b.w;
        if (relu) {
            v.x = fmaxf(v.x, 0.f); v.y = fmaxf(v.y, 0.f);
            v.z = fmaxf(v.z, 0.f); v.w = fmaxf(v.w, 0.f);
        }
        size_t go = (size_t)gr * D + col;
        if (fin) {
            *(float4*)(out + go) = v;
        } else {
            __half2 a0 = __floats2half2_rn(v.x, v.y);
            __half2 a1 = __floats2half2_rn(v.z, v.w);
            *(uint2*)(actout + go) = make_uint2(*(unsigned*)&a0, *(unsigned*)&a1);
        }
    }
}

// ---------------- launch ----------------
extern "C" void kernel_launch(void* const* d_in, const int* in_sizes, int n_in,
                              void* d_out, int out_size) {
    const float* x   = (const float*)d_in[0];
    const void*  ei  = d_in[1];
    const float* W1l = (const float*)d_in[2];
    const float* b1  = (const float*)d_in[3];
    const float* W1r = (const float*)d_in[4];
    const float* W2l = (const float*)d_in[5];
    const float* b2  = (const float*)d_in[6];
    const float* W2r = (const float*)d_in[7];
    const float* W3l = (const float*)d_in[8];
    const float* b3  = (const float*)d_in[9];
    const float* W3r = (const float*)d_in[10];
    float* out = (float*)d_out;

    int n = in_sizes[0] / D;
    int E = in_sizes[1] / 2;

    __half *actp, *aggp, *wp;
    int *cntp, *totp;
    cudaGetSymbolAddress((void**)&actp, g_act);
    cudaGetSymbolAddress((void**)&aggp, g_agg);
    cudaGetSymbolAddress((void**)&wp,   g_W);
    cudaGetSymbolAddress((void**)&cntp, g_cnt);
    cudaGetSymbolAddress((void**)&totp, g_tot);

    cudaFuncSetAttribute(gemm_kernel, cudaFuncAttributeMaxDynamicSharedMemorySize, SMEM_TOTAL);

    // CSR build
    detect_kernel<<<1, 256>>>(ei, E);
    cudaMemsetAsync(cntp, 0, (size_t)n * sizeof(int));
    cudaMemsetAsync(totp, 0, sizeof(int));
    int e4 = (E + 3) / 4;
    hist_kernel<<<(e4 + 255) / 256, 256>>>(ei, E);
    assign_kernel<<<(n + 255) / 256, 256>>>(n);
    fill_kernel<<<(e4 + 255) / 256, 256>>>(ei, E);

    // conversions
    wconv_kernel<<<(6 * D * D + 255) / 256, 256>>>(W1l, W1r, W2l, W2r, W3l, W3r);
    int total4 = n * D / 4;
    xconv_kernel<<<(total4 + 255) / 256, 256>>>(x, actp, total4);

    int agg_blocks  = (n * 32 + 255) / 256;
    int gemm_blocks = (n + 127) / 128;

    // layer 1
    agg_kernel<<<agg_blocks, 256>>>(actp, aggp, n);
    gemm_kernel<<<gemm_blocks, 256, SMEM_TOTAL>>>(aggp, actp,
        wp + 0 * D * D, wp + 1 * D * D, b1, out, actp, n, 1, 0);
    // layer 2
    agg_kernel<<<agg_blocks, 256>>>(actp, aggp, n);
    gemm_kernel<<<gemm_blocks, 256, SMEM_TOTAL>>>(aggp, actp,
        wp + 2 * D * D, wp + 3 * D * D, b2, out, actp, n, 1, 0);
    // layer 3 (final: fp32 out)
    agg_kernel<<<agg_blocks, 256>>>(actp, aggp, n);
    gemm_kernel<<<gemm_blocks, 256, SMEM_TOTAL>>>(aggp, actp,
        wp + 4 * D * D, wp + 5 * D * D, b3, out, actp, n, 0, 1);
}